// round 1
// baseline (speedup 1.0000x reference)
#include <cuda_runtime.h>
#include <math.h>

#define NB 32
#define NL 512
#define NHID 512
#define NH 8
#define NE 64
#define NTOPK 62
#define FLEFT 102
#define PI_D 3.14159265358979323846

// ---------------- static device scratch (no allocations allowed) ----------------
__device__ float d_g[NL];
__device__ float d_G[NL * NL];
__device__ float d_Q[NB * NL * NHID];
__device__ float d_K[NB * NL * NHID];
__device__ float d_V[NB * NL * NHID];
__device__ float d_Qf[NB * NL * NHID];
__device__ float d_Kf[NB * NL * NHID];
__device__ float d_Vf[NB * NL * NHID];
__device__ float d_P[NB * NL * NL];
__device__ float d_S[(size_t)NB * NH * NL * NL];  // 268MB scores/probs
__device__ float d_ctx[NB * NL * NHID];
__device__ float d_Hb[NB * NL * NHID];
__device__ int   d_delay[NB * NTOPK];
__device__ float d_w[NB * NTOPK];

// ---------------- filter construction ----------------
// g = irfft(band mask), band = bins [102, 257) incl. Nyquist 256
__global__ void build_g() {
    int d = threadIdx.x;  // 512 threads
    double s = 0.0;
    for (int f = FLEFT; f < 256; ++f)
        s += 2.0 * cos(2.0 * PI_D * (double)f * (double)d / 512.0);
    s += (d & 1) ? -1.0 : 1.0;  // f = 256 term: cos(pi*d)
    d_g[d] = (float)(s / 512.0);
}

__global__ void build_G() {
    int l = blockIdx.x, m = threadIdx.x;
    d_G[l * NL + m] = d_g[(l - m) & (NL - 1)];
}

// ---------------- generic fp32 SGEMM ----------------
// C = alpha * A*op(B) + beta*C (+ bias[col]) (+ resid[row,col])
// A: MxK row-major (lda). B: TB ? NxK : KxN row-major (ldb). C: MxN (ldc).
// batching: z -> (zb = z/Hd, zh = z%Hd); ptr += zb*offXb + zh*offXh.
template <int BM, int BN, int BK, int TM, int TN, bool TB>
__global__ void __launch_bounds__(256) sgemm(
    const float* __restrict__ Ag, const float* __restrict__ Bg, float* __restrict__ Cg,
    int lda, int ldb, int ldc,
    long long offAb, long long offAh, long long offBb, long long offBh,
    long long offCb, long long offCh, int Hd, int K,
    const float* __restrict__ bias, const float* __restrict__ resid,
    float alpha, float beta)
{
    int z = blockIdx.z;
    int zb = z / Hd, zh = z % Hd;
    const float* A = Ag + zb * offAb + zh * offAh;
    const float* B = Bg + zb * offBb + zh * offBh;
    float* C = Cg + zb * offCb + zh * offCh;

    __shared__ float As[BK][BM];
    __shared__ float Bs[BK][BN];

    const int tid = threadIdx.x;
    const int row0 = blockIdx.y * BM;
    const int col0 = blockIdx.x * BN;
    const int tx = tid % (BN / TN);
    const int ty = tid / (BN / TN);

    float acc[TM][TN];
#pragma unroll
    for (int i = 0; i < TM; i++)
#pragma unroll
        for (int j = 0; j < TN; j++) acc[i][j] = 0.f;

    const int aRow = tid / (BK / 4);
    const int aCol = (tid % (BK / 4)) * 4;
    const int btRow = tid / (BK / 4);
    const int btCol = (tid % (BK / 4)) * 4;
    const int bnRow = tid / (BN / 4);
    const int bnCol = (tid % (BN / 4)) * 4;

    for (int k0 = 0; k0 < K; k0 += BK) {
        float4 av = *reinterpret_cast<const float4*>(&A[(size_t)(row0 + aRow) * lda + k0 + aCol]);
        As[aCol + 0][aRow] = av.x;
        As[aCol + 1][aRow] = av.y;
        As[aCol + 2][aRow] = av.z;
        As[aCol + 3][aRow] = av.w;
        if (TB) {
            float4 bv = *reinterpret_cast<const float4*>(&B[(size_t)(col0 + btRow) * ldb + k0 + btCol]);
            Bs[btCol + 0][btRow] = bv.x;
            Bs[btCol + 1][btRow] = bv.y;
            Bs[btCol + 2][btRow] = bv.z;
            Bs[btCol + 3][btRow] = bv.w;
        } else {
            float4 bv = *reinterpret_cast<const float4*>(&B[(size_t)(k0 + bnRow) * ldb + col0 + bnCol]);
            *reinterpret_cast<float4*>(&Bs[bnRow][bnCol]) = bv;
        }
        __syncthreads();
#pragma unroll
        for (int kk = 0; kk < BK; kk++) {
            float ra[TM], rb[TN];
#pragma unroll
            for (int i = 0; i < TM; i += 4)
                *reinterpret_cast<float4*>(&ra[i]) = *reinterpret_cast<const float4*>(&As[kk][ty * TM + i]);
#pragma unroll
            for (int j = 0; j < TN; j += 4)
                *reinterpret_cast<float4*>(&rb[j]) = *reinterpret_cast<const float4*>(&Bs[kk][tx * TN + j]);
#pragma unroll
            for (int i = 0; i < TM; i++)
#pragma unroll
                for (int j = 0; j < TN; j++) acc[i][j] += ra[i] * rb[j];
        }
        __syncthreads();
    }

#pragma unroll
    for (int i = 0; i < TM; i++) {
        int r = row0 + ty * TM + i;
#pragma unroll
        for (int j = 0; j < TN; j++) {
            int c = col0 + tx * TN + j;
            float v = alpha * acc[i][j];
            if (beta != 0.f) v += beta * C[(size_t)r * ldc + c];
            if (bias) v += bias[c];
            if (resid) v += resid[(size_t)r * ldc + c];
            C[(size_t)r * ldc + c] = v;
        }
    }
}

// ---------------- mean_value + top-k + softmax(weights) ----------------
__global__ void meanvalue_topk(const float* __restrict__ P) {
    int b = blockIdx.x;
    int t = threadIdx.x;  // 256
    __shared__ float mv[NL];
    __shared__ float rv[256];
    __shared__ int ri[256];
    __shared__ float selw[NTOPK];
    __shared__ int seld[NTOPK];

    const float* Pb = P + (size_t)b * NL * NL;
    for (int d = t; d < NL; d += 256) {
        float s = 0.f;
        for (int l = 0; l < NL; l++) s += Pb[(size_t)((l + d) & (NL - 1)) * NL + l];
        mv[d] = s * (1.f / (float)NHID);
    }
    __syncthreads();

    for (int k = 0; k < NTOPK; k++) {
        float best = -1e30f;
        int bi = NL;
        for (int d = t; d < NL; d += 256) {
            float x = mv[d];
            if (x > best || (x == best && d < bi)) { best = x; bi = d; }
        }
        rv[t] = best;
        ri[t] = bi;
        __syncthreads();
        for (int off = 128; off; off >>= 1) {
            if (t < off) {
                if (rv[t + off] > rv[t] || (rv[t + off] == rv[t] && ri[t + off] < ri[t])) {
                    rv[t] = rv[t + off];
                    ri[t] = ri[t + off];
                }
            }
            __syncthreads();
        }
        if (t == 0) {
            selw[k] = rv[0];
            seld[k] = ri[0];
            mv[ri[0]] = -1e30f;
        }
        __syncthreads();
    }
    if (t == 0) {
        float m = selw[0];  // first selected = global max
        float s = 0.f;
        for (int k = 0; k < NTOPK; k++) {
            float e = expf(selw[k] - m);
            selw[k] = e;
            s += e;
        }
        float inv = 1.f / s;
        for (int k = 0; k < NTOPK; k++) {
            d_w[b * NTOPK + k] = selw[k] * inv;
            d_delay[b * NTOPK + k] = seld[k];
        }
    }
}

// ---------------- time-delay aggregation: ctx = 0.5 * sum_k w_k * V[(l+d_k)%L] ----------------
__global__ void delay_agg(const float* __restrict__ V, float* __restrict__ ctx) {
    int l = blockIdx.x, b = blockIdx.y;
    int t = threadIdx.x;  // 512 = NHID
    __shared__ float w[NTOPK];
    __shared__ int dl[NTOPK];
    if (t < NTOPK) {
        w[t] = d_w[b * NTOPK + t];
        dl[t] = d_delay[b * NTOPK + t];
    }
    __syncthreads();
    const float* Vb = V + (size_t)b * NL * NHID;
    float acc = 0.f;
#pragma unroll 2
    for (int k = 0; k < NTOPK; k++)
        acc += w[k] * Vb[(size_t)((l + dl[k]) & (NL - 1)) * NHID + t];
    ctx[(size_t)b * NL * NHID + (size_t)l * NHID + t] = 0.5f * acc;
}

// ---------------- row softmax with mask, in place over scores ----------------
__global__ void softmax_mask(float* __restrict__ S, const float* __restrict__ mask) {
    size_t row = blockIdx.x;  // b*H*L + h*L + i
    int b = (int)(row / (NH * NL));
    int i = (int)(row % NL);
    float* s = S + row * NL;
    const float* mrow = mask + (size_t)b * NL * NL + (size_t)i * NL;
    int t = threadIdx.x;  // 128

    float v[4];
    float mx = -1e30f;
#pragma unroll
    for (int k = 0; k < 4; k++) {
        v[k] = s[t + 128 * k] + mrow[t + 128 * k];
        mx = fmaxf(mx, v[k]);
    }
    __shared__ float red[32];
#pragma unroll
    for (int off = 16; off; off >>= 1) mx = fmaxf(mx, __shfl_xor_sync(0xffffffffu, mx, off));
    if ((t & 31) == 0) red[t >> 5] = mx;
    __syncthreads();
    if (t < 4) {
        float m2 = red[t];
#pragma unroll
        for (int off = 2; off; off >>= 1) m2 = fmaxf(m2, __shfl_xor_sync(0xfu, m2, off));
        red[t] = m2;
    }
    __syncthreads();
    mx = red[0];

    float sum = 0.f;
#pragma unroll
    for (int k = 0; k < 4; k++) {
        v[k] = expf(v[k] - mx);
        sum += v[k];
    }
#pragma unroll
    for (int off = 16; off; off >>= 1) sum += __shfl_xor_sync(0xffffffffu, sum, off);
    __syncthreads();
    if ((t & 31) == 0) red[t >> 5] = sum;
    __syncthreads();
    if (t < 4) {
        float s2 = red[t];
#pragma unroll
        for (int off = 2; off; off >>= 1) s2 += __shfl_xor_sync(0xfu, s2, off);
        red[t] = s2;
    }
    __syncthreads();
    float inv = 1.f / red[0];
#pragma unroll
    for (int k = 0; k < 4; k++) s[t + 128 * k] = v[k] * inv;
}

// ---------------- layernorm ----------------
__global__ void layernorm(const float* __restrict__ Hb, const float* __restrict__ w,
                          const float* __restrict__ bz, float* __restrict__ out) {
    size_t row = blockIdx.x;
    const float* h = Hb + row * NHID;
    float* o = out + row * NHID;
    int t = threadIdx.x;  // 128
    float v[4];
    float s = 0.f;
#pragma unroll
    for (int k = 0; k < 4; k++) {
        v[k] = h[t + 128 * k];
        s += v[k];
    }
    __shared__ float red[32];
    __shared__ float stat[2];
#pragma unroll
    for (int off = 16; off; off >>= 1) s += __shfl_xor_sync(0xffffffffu, s, off);
    if ((t & 31) == 0) red[t >> 5] = s;
    __syncthreads();
    if (t == 0) {
        float a = red[0] + red[1] + red[2] + red[3];
        stat[0] = a / (float)NHID;
    }
    __syncthreads();
    float mu = stat[0];
    float s2 = 0.f;
#pragma unroll
    for (int k = 0; k < 4; k++) {
        float d = v[k] - mu;
        s2 += d * d;
    }
#pragma unroll
    for (int off = 16; off; off >>= 1) s2 += __shfl_xor_sync(0xffffffffu, s2, off);
    __syncthreads();
    if ((t & 31) == 0) red[t >> 5] = s2;
    __syncthreads();
    if (t == 0) {
        float a = red[0] + red[1] + red[2] + red[3];
        stat[1] = 1.f / sqrtf(a / (float)NHID + 1e-12f);
    }
    __syncthreads();
    float inv = stat[1];
#pragma unroll
    for (int k = 0; k < 4; k++) {
        int c = t + 128 * k;
        o[c] = w[c] * ((v[k] - mu) * inv) + bz[c];
    }
}

// ---------------- launch ----------------
extern "C" void kernel_launch(void* const* d_in, const int* in_sizes, int n_in,
                              void* d_out, int out_size) {
    (void)in_sizes; (void)n_in; (void)out_size;
    const float* x    = (const float*)d_in[0];
    const float* mask = (const float*)d_in[1];
    const float* Wq = (const float*)d_in[2];
    const float* bq = (const float*)d_in[3];
    const float* Wk = (const float*)d_in[4];
    const float* bk = (const float*)d_in[5];
    const float* Wv = (const float*)d_in[6];
    const float* bv = (const float*)d_in[7];
    const float* Wd = (const float*)d_in[8];
    const float* bd = (const float*)d_in[9];
    const float* lnw = (const float*)d_in[10];
    const float* lnb = (const float*)d_in[11];
    float* out = (float*)d_out;

    float *pQ, *pK, *pV, *pQf, *pKf, *pVf, *pP, *pS, *pCtx, *pH, *pG;
    cudaGetSymbolAddress((void**)&pQ, d_Q);
    cudaGetSymbolAddress((void**)&pK, d_K);
    cudaGetSymbolAddress((void**)&pV, d_V);
    cudaGetSymbolAddress((void**)&pQf, d_Qf);
    cudaGetSymbolAddress((void**)&pKf, d_Kf);
    cudaGetSymbolAddress((void**)&pVf, d_Vf);
    cudaGetSymbolAddress((void**)&pP, d_P);
    cudaGetSymbolAddress((void**)&pS, d_S);
    cudaGetSymbolAddress((void**)&pCtx, d_ctx);
    cudaGetSymbolAddress((void**)&pH, d_Hb);
    cudaGetSymbolAddress((void**)&pG, d_G);

    const long long BLH = (long long)NL * NHID;      // 262144
    const long long BLL = (long long)NL * NL;        // 262144

    build_g<<<1, NL>>>();
    build_G<<<NL, NL>>>();

    // QKV projections: [16384,512] = x @ W^T + b   (NT)
    dim3 gb(NHID / 128, (NB * NL) / 128, 1);
    sgemm<128, 128, 8, 8, 8, true><<<gb, 256>>>(x, Wq, pQ, NHID, NHID, NHID,
        0, 0, 0, 0, 0, 0, 1, NHID, bq, nullptr, 1.f, 0.f);
    sgemm<128, 128, 8, 8, 8, true><<<gb, 256>>>(x, Wk, pK, NHID, NHID, NHID,
        0, 0, 0, 0, 0, 0, 1, NHID, bk, nullptr, 1.f, 0.f);
    sgemm<128, 128, 8, 8, 8, true><<<gb, 256>>>(x, Wv, pV, NHID, NHID, NHID,
        0, 0, 0, 0, 0, 0, 1, NHID, bv, nullptr, 1.f, 0.f);

    // band-limit filters: Xf_b = G @ X_b  (NN, batched over B)
    dim3 gf(NHID / 128, NL / 128, NB);
    sgemm<128, 128, 8, 8, 8, false><<<gf, 256>>>(pG, pQ, pQf, NL, NHID, NHID,
        0, 0, BLH, 0, BLH, 0, 1, NL, nullptr, nullptr, 1.f, 0.f);
    sgemm<128, 128, 8, 8, 8, false><<<gf, 256>>>(pG, pK, pKf, NL, NHID, NHID,
        0, 0, BLH, 0, BLH, 0, 1, NL, nullptr, nullptr, 1.f, 0.f);
    sgemm<128, 128, 8, 8, 8, false><<<gf, 256>>>(pG, pV, pVf, NL, NHID, NHID,
        0, 0, BLH, 0, BLH, 0, 1, NL, nullptr, nullptr, 1.f, 0.f);

    // P_b = Qf_b @ Kf_b^T over all 512 channels (NT, batched)
    dim3 gp(NL / 128, NL / 128, NB);
    sgemm<128, 128, 8, 8, 8, true><<<gp, 256>>>(pQf, pKf, pP, NHID, NHID, NL,
        BLH, 0, BLH, 0, BLL, 0, 1, NHID, nullptr, nullptr, 1.f, 0.f);

    // mean over channels via diagonal sums of P, top-62, softmax of weights
    meanvalue_topk<<<NB, 256>>>(pP);

    // time branch: ctx = 0.5 * weighted circular gather of V
    delay_agg<<<dim3(NL, NB), NHID>>>(pV, pCtx);

    // per-head attention scores: S[z=b*8+h] = (1/8) Qf_h @ Kf_h^T  (NT, K=64)
    dim3 gs(NL / 128, NL / 128, NB * NH);
    sgemm<128, 128, 8, 8, 8, true><<<gs, 256>>>(pQf, pKf, pS, NHID, NHID, NL,
        BLH, NE, BLH, NE, (long long)NH * BLL, BLL, NH, NE,
        nullptr, nullptr, 0.125f, 0.f);

    // softmax rows (+ attention mask)
    softmax_mask<<<NB * NH * NL, 128>>>(pS, mask);

    // ctx += 0.5 * probs @ Vf_h  (NN, N=64, beta=1 accumulates onto time branch)
    dim3 gc(NE / 64, NL / 64, NB * NH);
    sgemm<64, 64, 16, 4, 4, false><<<gc, 256>>>(pS, pVf, pCtx, NL, NHID, NHID,
        (long long)NH * BLL, BLL, BLH, NE, BLH, NE, NH, NL,
        nullptr, nullptr, 0.5f, 1.f);

    // output projection + bias + residual
    sgemm<128, 128, 8, 8, 8, true><<<gb, 256>>>(pCtx, Wd, pH, NHID, NHID, NHID,
        0, 0, 0, 0, 0, 0, 1, NHID, bd, x, 1.f, 0.f);

    // layernorm
    layernorm<<<NB * NL, 128>>>(pH, lnw, lnb, out);
}

// round 6
// speedup vs baseline: 1.7293x; 1.7293x over previous
#include <cuda_runtime.h>
#include <cuda_bf16.h>
#include <math.h>
#include <stdint.h>

#define NB 32
#define NL 512
#define NHID 512
#define NH 8
#define NE 64
#define NTOPK 62
#define FLEFT 102
#define PI_D 3.14159265358979323846

typedef __nv_bfloat16 bf16;

// ---------------- static device scratch ----------------
__device__ float d_g[NL];
__device__ float d_bqkv[3 * NHID];
__device__ bf16 d_We[3 * NHID * 3 * NHID];
__device__ bf16 d_Wde[NHID * 3 * NHID];
__device__ bf16 d_xe[NB * NL * 3 * NHID];
__device__ bf16 d_Ge[NL * 3 * NL];
__device__ float d_QKV[(size_t)NB * NL * 3 * NHID];
__device__ bf16 d_QKVte[(size_t)NB * 1536 * 1536];
__device__ float d_Xf[(size_t)NB * NL * 3 * NHID];
__device__ bf16 d_Qfe[(size_t)NB * NH * NL * 192];
__device__ bf16 d_Kfe[(size_t)NB * NH * NL * 192];
__device__ bf16 d_Vfte[(size_t)NB * NH * NE * 1536];
__device__ float d_S[(size_t)NB * NH * NL * NL];
__device__ bf16 d_Se[(size_t)NB * NH * NL * 1536];
__device__ float d_ctx[(size_t)NB * NL * NHID];
__device__ bf16 d_ctxe[(size_t)NB * NL * 1536];
__device__ float d_Hb[(size_t)NB * NL * NHID];
__device__ float d_mvp[NB * NH * NL];
__device__ int d_delay[NB * NTOPK];
__device__ float d_w[NB * NTOPK];

// ---------------- helpers ----------------
__device__ __forceinline__ uint32_t smem_u32(const void* p) {
    uint32_t r;
    asm("{ .reg .u64 t; cvta.to.shared.u64 t, %1; cvt.u32.u64 %0, t; }" : "=r"(r) : "l"(p));
    return r;
}
__device__ __forceinline__ void cpa16(uint32_t s, const void* g) {
    asm volatile("cp.async.cg.shared.global [%0], [%1], 16;\n" :: "r"(s), "l"(g));
}
__device__ __forceinline__ void ldm_x4(uint32_t& r0, uint32_t& r1, uint32_t& r2, uint32_t& r3,
                                       uint32_t a) {
    asm volatile("ldmatrix.sync.aligned.m8n8.x4.shared.b16 {%0,%1,%2,%3}, [%4];\n"
                 : "=r"(r0), "=r"(r1), "=r"(r2), "=r"(r3) : "r"(a));
}
__device__ __forceinline__ void mma16816(float* c, const uint32_t* a, const uint32_t* b) {
    asm volatile(
        "mma.sync.aligned.m16n8k16.row.col.f32.bf16.bf16.f32 "
        "{%0,%1,%2,%3},{%4,%5,%6,%7},{%8,%9},{%0,%1,%2,%3};\n"
        : "+f"(c[0]), "+f"(c[1]), "+f"(c[2]), "+f"(c[3])
        : "r"(a[0]), "r"(a[1]), "r"(a[2]), "r"(a[3]), "r"(b[0]), "r"(b[1]));
}

// ---------------- bf16 HMMA NT GEMM over expanded-K operands ----------------
// C[M,N](f32) = alpha*A[M,Kx]·B[N,Kx]^T (+beta*C)(+bias[col])(+resid)
template <int BN>
__global__ void __launch_bounds__(256, 2) bgemm(
    const bf16* __restrict__ Ag, const bf16* __restrict__ Bg, float* __restrict__ Cg,
    int lda, int ldb, int ldc, int Kx,
    long long oAb, long long oAh, long long oBb, long long oBh,
    long long oCb, long long oCh, int Hd,
    const float* __restrict__ bias, const float* __restrict__ resid,
    float alpha, float beta)
{
    constexpr int BM = 128, LT = 72;          // 64 bf16 + 8 pad per row
    constexpr int ASTG = BM * LT * 2;         // bytes per A stage
    constexpr int BSTG = BN * LT * 2;
    constexpr int NT = BN / 16;               // 8x8 n-tiles per warp
    const int NC = Kx >> 6;

    extern __shared__ bf16 sm[];
    const uint32_t sbase = smem_u32(sm);

    const int tid = threadIdx.x;
    const int lane = tid & 31, warp = tid >> 5;
    const int wm = warp >> 1, wn = warp & 1;  // 4 x 2 warp grid

    const int z = blockIdx.z, zb = z / Hd, zh = z % Hd;
    const int row0 = blockIdx.y * BM, col0 = blockIdx.x * BN;
    const int lda2 = lda * 2, ldb2 = ldb * 2;
    const char* A = (const char*)(Ag + zb * oAb + zh * oAh) + (size_t)row0 * lda2;
    const char* B = (const char*)(Bg + zb * oBb + zh * oBh) + (size_t)col0 * ldb2;
    float* C = Cg + zb * oCb + zh * oCh;

    float acc[2][NT][4];
#pragma unroll
    for (int i = 0; i < 2; i++)
#pragma unroll
        for (int j = 0; j < NT; j++)
#pragma unroll
            for (int k = 0; k < 4; k++) acc[i][j][k] = 0.f;

    auto load_stage = [&](int c) {
        int s = c & 1;
        uint32_t sa = sbase + s * ASTG;
        const char* Ac = A + c * 128;
#pragma unroll
        for (int i = 0; i < (BM * 8) / 256; i++) {
            int cc = tid + i * 256, r = cc >> 3, sg = (cc & 7) * 16;
            cpa16(sa + r * (LT * 2) + sg, Ac + (size_t)r * lda2 + sg);
        }
        uint32_t sb = sbase + 2 * ASTG + s * BSTG;
        const char* Bc = B + c * 128;
#pragma unroll
        for (int i = 0; i < (BN * 8) / 256; i++) {
            int cc = tid + i * 256, r = cc >> 3, sg = (cc & 7) * 16;
            cpa16(sb + r * (LT * 2) + sg, Bc + (size_t)r * ldb2 + sg);
        }
        asm volatile("cp.async.commit_group;\n");
    };

    load_stage(0);

    const int g = lane >> 3, ri = lane & 7;
    for (int c = 0; c < NC; c++) {
        if (c + 1 < NC) {
            load_stage(c + 1);
            asm volatile("cp.async.wait_group 1;\n");
        } else {
            asm volatile("cp.async.wait_group 0;\n");
        }
        __syncthreads();

        int s = c & 1;
        uint32_t sa = sbase + s * ASTG;
        uint32_t sb = sbase + 2 * ASTG + s * BSTG;
#pragma unroll
        for (int k16 = 0; k16 < 4; k16++) {
            uint32_t a[2][4];
#pragma unroll
            for (int mt = 0; mt < 2; mt++) {
                int row = wm * 32 + mt * 16 + ri + (g & 1) * 8;
                ldm_x4(a[mt][0], a[mt][1], a[mt][2], a[mt][3],
                       sa + row * (LT * 2) + k16 * 32 + (g >> 1) * 16);
            }
            uint32_t b[NT][2];
#pragma unroll
            for (int np = 0; np < NT / 2; np++) {
                int nrow = wn * (BN / 2) + np * 16 + ri + (g >> 1) * 8;
                ldm_x4(b[2 * np][0], b[2 * np][1], b[2 * np + 1][0], b[2 * np + 1][1],
                       sb + nrow * (LT * 2) + k16 * 32 + (g & 1) * 16);
            }
#pragma unroll
            for (int mt = 0; mt < 2; mt++)
#pragma unroll
                for (int nt = 0; nt < NT; nt++)
                    mma16816(acc[mt][nt], a[mt], b[nt]);
        }
        __syncthreads();
    }

    // epilogue: per-thread fragment stores with fused ops
    const int gq = lane >> 2, tq = lane & 3;
#pragma unroll
    for (int mt = 0; mt < 2; mt++) {
#pragma unroll
        for (int nt = 0; nt < NT; nt++) {
            int ccol = col0 + wn * (BN / 2) + nt * 8 + tq * 2;
#pragma unroll
            for (int h = 0; h < 2; h++) {
                int r = row0 + wm * 32 + mt * 16 + gq + h * 8;
                size_t off = (size_t)r * ldc + ccol;
                float v0 = alpha * acc[mt][nt][2 * h];
                float v1 = alpha * acc[mt][nt][2 * h + 1];
                if (beta != 0.f) {
                    float2 p = *(const float2*)&C[off];
                    v0 += beta * p.x; v1 += beta * p.y;
                }
                if (bias) { v0 += bias[ccol]; v1 += bias[ccol + 1]; }
                if (resid) {
                    float2 p = *(const float2*)&resid[off];
                    v0 += p.x; v1 += p.y;
                }
                float2 o; o.x = v0; o.y = v1;
                *(float2*)&C[off] = o;
            }
        }
    }
}

// ---------------- setup + expansions ----------------
__global__ void setup_misc(const float* bq, const float* bk, const float* bv) {
    int t = threadIdx.x;
    double s = 0.0;
    for (int f = FLEFT; f < 256; ++f)
        s += 2.0 * cos(2.0 * PI_D * (double)f * (double)t / 512.0);
    s += (t & 1) ? -1.0 : 1.0;
    d_g[t] = (float)(s / 512.0);
    d_bqkv[t] = bq[t]; d_bqkv[512 + t] = bk[t]; d_bqkv[1024 + t] = bv[t];
}
__global__ void expand_G() {
    int l = blockIdx.x, m = threadIdx.x;
    float v = d_g[(l - m) & (NL - 1)];
    bf16 h = __float2bfloat16(v);
    bf16 lo = __float2bfloat16(v - __bfloat162float(h));
    bf16* d = d_Ge + (size_t)l * 1536 + 3 * m;
    d[0] = h; d[1] = lo; d[2] = h;
}
// PAT 0 = A-pattern (hi,lo,hi); PAT 1 = B-pattern (hi,hi,lo)
template <int PAT>
__global__ void expand_k(const float* __restrict__ src, bf16* __restrict__ dst,
                         int K, int src_ld, int Hd, long long oZb, long long oZh, long long dstZ) {
    int z = blockIdx.z, zb = z / Hd, zh = z % Hd;
    const float* s = src + zb * oZb + zh * oZh + (size_t)blockIdx.y * src_ld;
    bf16* d = dst + (size_t)z * dstZ + (size_t)blockIdx.y * (3 * K);
    for (int k = blockIdx.x * blockDim.x + threadIdx.x; k < K; k += gridDim.x * blockDim.x) {
        float v = s[k];
        bf16 h = __float2bfloat16(v);
        bf16 lo = __float2bfloat16(v - __bfloat162float(h));
        if (PAT == 0) { d[3*k] = h; d[3*k+1] = lo; d[3*k+2] = h; }
        else          { d[3*k] = h; d[3*k+1] = h;  d[3*k+2] = lo; }
    }
}
// transpose + B-pattern: src [Krows, Ncols] -> dst [Ncols, 3*Krows]
__global__ void texpand_b(const float* __restrict__ src, bf16* __restrict__ dst,
                          int src_ld, int Krows, int Ncols, int Hd,
                          long long oZb, long long oZh, long long dstZ) {
    __shared__ float t[32][33];
    int z = blockIdx.z, zb = z / Hd, zh = z % Hd;
    const float* s = src + zb * oZb + zh * oZh;
    bf16* d = dst + (size_t)z * dstZ;
    int k0 = blockIdx.x * 32, n0 = blockIdx.y * 32;
    int tx = threadIdx.x, ty = threadIdx.y;
#pragma unroll
    for (int i = 0; i < 32; i += 8)
        t[ty + i][tx] = s[(size_t)(k0 + ty + i) * src_ld + n0 + tx];
    __syncthreads();
#pragma unroll
    for (int i = 0; i < 32; i += 8) {
        int n = n0 + ty + i, k = k0 + tx;
        float v = t[tx][ty + i];
        bf16 h = __float2bfloat16(v);
        bf16 lo = __float2bfloat16(v - __bfloat162float(h));
        bf16* dd = d + (size_t)n * (3 * Krows) + 3 * k;
        dd[0] = h; dd[1] = h; dd[2] = lo;
    }
}

// ---------------- mean_value from scores: circular-diagonal sums ----------------
__global__ void diag_partial(const float* __restrict__ S) {
    int h = blockIdx.x, b = blockIdx.y;
    const float* Sz = S + ((size_t)(b * NH + h)) * NL * NL;
    __shared__ float bins[8][NL];
    int wid = threadIdx.x >> 5, lane = threadIdx.x & 31;
    for (int i = threadIdx.x; i < 8 * NL; i += 256) ((float*)bins)[i] = 0.f;
    __syncthreads();
    for (int r = wid; r < NL; r += 8) {
        const float* row = Sz + (size_t)r * NL;
        for (int j = lane; j < NL; j += 32)
            bins[wid][(r - j) & (NL - 1)] += row[j];
    }
    __syncthreads();
    for (int dd = threadIdx.x; dd < NL; dd += 256) {
        float a = 0.f;
#pragma unroll
        for (int w = 0; w < 8; w++) a += bins[w][dd];
        d_mvp[(b * NH + h) * NL + dd] = a;
    }
}
__global__ void topk_kernel() {
    int b = blockIdx.x, t = threadIdx.x;
    __shared__ float mv[NL], rv[256], selw[NTOPK];
    __shared__ int ri[256], seld[NTOPK];
    for (int d = t; d < NL; d += 256) {
        float s = 0.f;
#pragma unroll
        for (int h = 0; h < NH; h++) s += d_mvp[(b * NH + h) * NL + d];
        mv[d] = s * (1.f / 64.f);  // corr = 8*S, mean over 512 channels
    }
    __syncthreads();
    for (int k = 0; k < NTOPK; k++) {
        float best = -1e30f; int bi = NL;
        for (int d = t; d < NL; d += 256) {
            float x = mv[d];
            if (x > best || (x == best && d < bi)) { best = x; bi = d; }
        }
        rv[t] = best; ri[t] = bi;
        __syncthreads();
        for (int off = 128; off; off >>= 1) {
            if (t < off && (rv[t+off] > rv[t] || (rv[t+off] == rv[t] && ri[t+off] < ri[t]))) {
                rv[t] = rv[t+off]; ri[t] = ri[t+off];
            }
            __syncthreads();
        }
        if (t == 0) { selw[k] = rv[0]; seld[k] = ri[0]; mv[ri[0]] = -1e30f; }
        __syncthreads();
    }
    if (t == 0) {
        float m = selw[0], s = 0.f;
        for (int k = 0; k < NTOPK; k++) { float e = expf(selw[k] - m); selw[k] = e; s += e; }
        float inv = 1.f / s;
        for (int k = 0; k < NTOPK; k++) {
            d_w[b * NTOPK + k] = selw[k] * inv;
            d_delay[b * NTOPK + k] = seld[k];
        }
    }
}

__global__ void delay_agg(const float* __restrict__ QKV, float* __restrict__ ctx) {
    int l = blockIdx.x, b = blockIdx.y, t = threadIdx.x;
    __shared__ float w[NTOPK];
    __shared__ int dl[NTOPK];
    if (t < NTOPK) { w[t] = d_w[b * NTOPK + t]; dl[t] = d_delay[b * NTOPK + t]; }
    __syncthreads();
    const float* Vb = QKV + (size_t)b * NL * 1536 + 1024 + t;
    float acc = 0.f;
#pragma unroll 2
    for (int k = 0; k < NTOPK; k++)
        acc += w[k] * Vb[(size_t)((l + dl[k]) & (NL - 1)) * 1536];
    ctx[(size_t)b * NL * NHID + (size_t)l * NHID + t] = 0.5f * acc;
}

__global__ void softmax_mask(float* __restrict__ S, const float* __restrict__ mask) {
    size_t row = blockIdx.x;
    int b = (int)(row / (NH * NL)), i = (int)(row % NL);
    float* s = S + row * NL;
    const float* mr = mask + (size_t)b * NL * NL + (size_t)i * NL;
    int t = threadIdx.x;
    float v[4], mx = -1e30f;
#pragma unroll
    for (int k = 0; k < 4; k++) { v[k] = s[t + 128*k] + mr[t + 128*k]; mx = fmaxf(mx, v[k]); }
    __shared__ float red[32];
#pragma unroll
    for (int o = 16; o; o >>= 1) mx = fmaxf(mx, __shfl_xor_sync(~0u, mx, o));
    if ((t & 31) == 0) red[t >> 5] = mx;
    __syncthreads();
    mx = fmaxf(fmaxf(red[0], red[1]), fmaxf(red[2], red[3]));
    float sum = 0.f;
#pragma unroll
    for (int k = 0; k < 4; k++) { v[k] = expf(v[k] - mx); sum += v[k]; }
#pragma unroll
    for (int o = 16; o; o >>= 1) sum += __shfl_xor_sync(~0u, sum, o);
    __syncthreads();
    if ((t & 31) == 0) red[t >> 5] = sum;
    __syncthreads();
    float inv = 1.f / (red[0] + red[1] + red[2] + red[3]);
#pragma unroll
    for (int k = 0; k < 4; k++) s[t + 128*k] = v[k] * inv;
}

__global__ void layernorm(const float* __restrict__ Hb, const float* __restrict__ w,
                          const float* __restrict__ bz, float* __restrict__ out) {
    size_t row = blockIdx.x;
    const float* h = Hb + row * NHID;
    float* o = out + row * NHID;
    int t = threadIdx.x;
    float v[4], s = 0.f;
#pragma unroll
    for (int k = 0; k < 4; k++) { v[k] = h[t + 128*k]; s += v[k]; }
    __shared__ float red[32];
#pragma unroll
    for (int o2 = 16; o2; o2 >>= 1) s += __shfl_xor_sync(~0u, s, o2);
    if ((t & 31) == 0) red[t >> 5] = s;
    __syncthreads();
    float mu = (red[0] + red[1] + red[2] + red[3]) / (float)NHID;
    float s2 = 0.f;
#pragma unroll
    for (int k = 0; k < 4; k++) { float d = v[k] - mu; s2 += d * d; }
#pragma unroll
    for (int o2 = 16; o2; o2 >>= 1) s2 += __shfl_xor_sync(~0u, s2, o2);
    __syncthreads();
    if ((t & 31) == 0) red[t >> 5] = s2;
    __syncthreads();
    float inv = rsqrtf((red[0] + red[1] + red[2] + red[3]) / (float)NHID + 1e-12f);
#pragma unroll
    for (int k = 0; k < 4; k++) {
        int c = t + 128*k;
        o[c] = w[c] * ((v[k] - mu) * inv) + bz[c];
    }
}

// ---------------- launch ----------------
extern "C" void kernel_launch(void* const* d_in, const int* in_sizes, int n_in,
                              void* d_out, int out_size) {
    (void)in_sizes; (void)n_in; (void)out_size;
    const float* x = (const float*)d_in[0];
    const float* mask = (const float*)d_in[1];
    const float* Wq = (const float*)d_in[2];
    const float* bq = (const float*)d_in[3];
    const float* Wk = (const float*)d_in[4];
    const float* bk = (const float*)d_in[5];
    const float* Wv = (const float*)d_in[6];
    const float* bv = (const float*)d_in[7];
    const float* Wd = (const float*)d_in[8];
    const float* bd = (const float*)d_in[9];
    const float* lnw = (const float*)d_in[10];
    const float* lnb = (const float*)d_in[11];
    float* out = (float*)d_out;

    bf16 *pWe, *pWde, *pxe, *pGe, *pQKVte, *pQfe, *pKfe, *pVfte, *pSe, *pctxe;
    float *pQKV, *pXf, *pS, *pctx, *pHb, *pbqkv;
    cudaGetSymbolAddress((void**)&pWe, d_We);
    cudaGetSymbolAddress((void**)&pWde, d_Wde);
    cudaGetSymbolAddress((void**)&pxe, d_xe);
    cudaGetSymbolAddress((void**)&pGe, d_Ge);
    cudaGetSymbolAddress((void**)&pQKVte, d_QKVte);
    cudaGetSymbolAddress((void**)&pQfe, d_Qfe);
    cudaGetSymbolAddress((void**)&pKfe, d_Kfe);
    cudaGetSymbolAddress((void**)&pVfte, d_Vfte);
    cudaGetSymbolAddress((void**)&pSe, d_Se);
    cudaGetSymbolAddress((void**)&pctxe, d_ctxe);
    cudaGetSymbolAddress((void**)&pQKV, d_QKV);
    cudaGetSymbolAddress((void**)&pXf, d_Xf);
    cudaGetSymbolAddress((void**)&pS, d_S);
    cudaGetSymbolAddress((void**)&pctx, d_ctx);
    cudaGetSymbolAddress((void**)&pHb, d_Hb);
    cudaGetSymbolAddress((void**)&pbqkv, d_bqkv);

    const int SM128 = (2 * 128 + 2 * 128) * 72 * 2;  // 73728 B
    const int SM64  = (2 * 128 + 2 * 64) * 72 * 2;   // 55296 B
    cudaFuncSetAttribute(bgemm<128>, cudaFuncAttributeMaxDynamicSharedMemorySize, SM128);
    cudaFuncSetAttribute(bgemm<64>,  cudaFuncAttributeMaxDynamicSharedMemorySize, SM64);

    const long long L1536 = 1536LL * 512;
    const long long BLH = 512LL * 512;
    const long long BLL = 512LL * 512;

    setup_misc<<<1, 512>>>(bq, bk, bv);
    expand_G<<<512, 512>>>();
    expand_k<1><<<dim3(2,512,1), 256>>>(Wq, pWe,             512, 512, 1, 0, 0, 0);
    expand_k<1><<<dim3(2,512,1), 256>>>(Wk, pWe + 512*1536,  512, 512, 1, 0, 0, 0);
    expand_k<1><<<dim3(2,512,1), 256>>>(Wv, pWe + 1024*1536, 512, 512, 1, 0, 0, 0);
    expand_k<1><<<dim3(2,512,1), 256>>>(Wd, pWde,            512, 512, 1, 0, 0, 0);
    expand_k<0><<<dim3(2,16384,1), 256>>>(x, pxe,            512, 512, 1, 0, 0, 0);

    // 1) fused QKV projection: QKV[16384,1536] = x @ [Wq;Wk;Wv]^T + b
    bgemm<128><<<dim3(12,128,1), 256, SM128>>>(pxe, pWe, pQKV,
        1536, 1536, 1536, 1536, 0,0, 0,0, 0,0, 1, pbqkv, nullptr, 1.f, 0.f);

    // transpose+expand QKV per batch -> [1536, 1536]
    texpand_b<<<dim3(16,48,32), dim3(32,8)>>>(pQKV, pQKVte, 1536, 512, 1536, 1,
        L1536, 0, 1536LL*1536);

    // 2) band-limit filter: Xf[b] = G @ QKV[b]
    bgemm<128><<<dim3(12,4,32), 256, SM128>>>(pGe, pQKVte, pXf,
        1536, 1536, 1536, 1536, 0,0, 1536LL*1536,0, L1536,0, 1, nullptr, nullptr, 1.f, 0.f);

    // per-head expansions
    expand_k<0><<<dim3(1,512,256), 64>>>(pXf, pQfe, 64, 1536, 8, L1536, 64, 512LL*192);
    expand_k<1><<<dim3(1,512,256), 64>>>(pXf + 512, pKfe, 64, 1536, 8, L1536, 64, 512LL*192);
    texpand_b<<<dim3(16,2,256), dim3(32,8)>>>(pXf + 1024, pVfte, 1536, 512, 64, 8,
        L1536, 64, 64LL*1536);

    // 3) scores: S[z] = 0.125 * Qf_h @ Kf_h^T
    bgemm<128><<<dim3(4,4,256), 256, SM128>>>(pQfe, pKfe, pS,
        192, 192, 512, 192, 8*512LL*192, 512LL*192, 8*512LL*192, 512LL*192,
        8*BLL, BLL, 8, nullptr, nullptr, 0.125f, 0.f);

    // mean_value from S diagonals; top-k; weights
    diag_partial<<<dim3(NH, NB), 256>>>(pS);
    topk_kernel<<<NB, 256>>>();

    // time branch gather (uses unfiltered V inside QKV, cols 1024..1535)
    delay_agg<<<dim3(NL, NB), NHID>>>(pQKV, pctx);

    // softmax (+mask), then expand probs
    softmax_mask<<<NB * NH * NL, 128>>>(pS, mask);
    expand_k<0><<<dim3(2,512,256), 256>>>(pS, pSe, 512, 512, 8, 8*BLL, BLL, 512LL*1536);

    // 4) ctx += 0.5 * probs @ Vf_h
    bgemm<64><<<dim3(1,4,256), 256, SM64>>>(pSe, pVfte, pctx,
        1536, 1536, 512, 1536, 8*512LL*1536, 512LL*1536, 8*64LL*1536, 64LL*1536,
        BLH, 64, 8, nullptr, nullptr, 0.5f, 1.f);

    // 5) output projection + bias + residual
    expand_k<0><<<dim3(2,16384,1), 256>>>(pctx, pctxe, 512, 512, 1, 0, 0, 0);
    bgemm<128><<<dim3(4,128,1), 256, SM128>>>(pctxe, pWde, pHb,
        1536, 1536, 512, 1536, 0,0, 0,0, 0,0, 1, bd, x, 1.f, 0.f);

    layernorm<<<NB * NL, 128>>>(pHb, lnw, lnb, out);
}

// round 8
// speedup vs baseline: 1.9822x; 1.1462x over previous
#include <cuda_runtime.h>
#include <cuda_bf16.h>
#include <math.h>
#include <stdint.h>

#define NB 32
#define NL 512
#define NHID 512
#define NH 8
#define NE 64
#define NTOPK 62
#define FLEFT 102
#define PI_D 3.14159265358979323846

typedef __nv_bfloat16 bf16;

// ---------------- static device scratch ----------------
__device__ float d_g[NL];
__device__ bf16 d_We[1536 * 1536];                 // [Wq;Wk;Wv] expanded (B-pattern)
__device__ bf16 d_Wde[512 * 1536];                 // Wd expanded (B-pattern)
__device__ bf16 d_xe[16384 * 1536];                // x expanded (A-pattern)
__device__ bf16 d_Ge[512 * 1536];                  // G expanded (A-pattern)
__device__ bf16 d_xte[(size_t)NB * 512 * 1536];    // x^T expanded (B-pattern), per batch
__device__ float d_Xg[(size_t)NB * 512 * 512];     // filtered X (f32)
__device__ bf16 d_Xge[16384 * 1536];               // filtered X expanded (A-pattern, via expA)
__device__ float d_QKVf[(size_t)16384 * 1536];     // Qf|Kf|Vf (f32)
__device__ float d_V[(size_t)16384 * 512];         // unfiltered V (time branch)
__device__ bf16 d_Qfe[(size_t)NB * NH * NL * 192];
__device__ bf16 d_Kfe[(size_t)NB * NH * NL * 192];
__device__ bf16 d_Vfte[(size_t)NB * NH * NE * 1536];
__device__ float d_S[(size_t)NB * NH * NL * NL];   // raw scores (pre-softmax)
__device__ bf16 d_Se[(size_t)NB * NH * NL * 1536]; // probs expanded (A-pattern)
__device__ float d_ctx[(size_t)16384 * 512];
__device__ bf16 d_ctxe[(size_t)16384 * 1536];      // ctx expanded (A-pattern, via expA)
__device__ float d_Hb[(size_t)16384 * 512];
__device__ float d_mvp[NB * NH * NL];
__device__ int d_delay[NB * NTOPK];
__device__ float d_w[NB * NTOPK];

// ---------------- helpers ----------------
__device__ __forceinline__ uint32_t smem_u32(const void* p) {
    uint32_t r;
    asm("{ .reg .u64 t; cvta.to.shared.u64 t, %1; cvt.u32.u64 %0, t; }" : "=r"(r) : "l"(p));
    return r;
}
__device__ __forceinline__ void cpa16(uint32_t s, const void* g) {
    asm volatile("cp.async.cg.shared.global [%0], [%1], 16;\n" :: "r"(s), "l"(g));
}
__device__ __forceinline__ void ldm_x4(uint32_t& r0, uint32_t& r1, uint32_t& r2, uint32_t& r3,
                                       uint32_t a) {
    asm volatile("ldmatrix.sync.aligned.m8n8.x4.shared.b16 {%0,%1,%2,%3}, [%4];\n"
                 : "=r"(r0), "=r"(r1), "=r"(r2), "=r"(r3) : "r"(a));
}
__device__ __forceinline__ void mma16816(float* c, const uint32_t* a, const uint32_t* b) {
    asm volatile(
        "mma.sync.aligned.m16n8k16.row.col.f32.bf16.bf16.f32 "
        "{%0,%1,%2,%3},{%4,%5,%6,%7},{%8,%9},{%0,%1,%2,%3};\n"
        : "+f"(c[0]), "+f"(c[1]), "+f"(c[2]), "+f"(c[3])
        : "r"(a[0]), "r"(a[1]), "r"(a[2]), "r"(a[3]), "r"(b[0]), "r"(b[1]));
}
__device__ __forceinline__ unsigned short bfbits(bf16 h) {
    return __bfloat16_as_ushort(h);
}

// ---------------- bf16 HMMA NT GEMM over expanded-K operands ----------------
// C[M,N](f32) = alpha*A[M,Kx]·B[N,Kx]^T (+beta*C)(+bias[col])(+resid)
// optional expA: also emit A-pattern (hi,lo,hi) bf16 triplets of the final C value.
template <int BN>
__global__ void __launch_bounds__(256, 2) bgemm(
    const bf16* __restrict__ Ag, const bf16* __restrict__ Bg, float* __restrict__ Cg,
    int lda, int ldb, int ldc, int Kx,
    long long oAb, long long oAh, long long oBb, long long oBh,
    long long oCb, long long oCh, int Hd,
    const float* __restrict__ bias, const float* __restrict__ resid,
    bf16* __restrict__ expAg,
    float alpha, float beta)
{
    constexpr int BM = 128, LT = 72;          // 64 bf16 + 8 pad per row
    constexpr int ASTG = BM * LT * 2;
    constexpr int BSTG = BN * LT * 2;
    constexpr int NT = BN / 16;
    const int NC = Kx >> 6;

    extern __shared__ bf16 sm[];
    const uint32_t sbase = smem_u32(sm);

    const int tid = threadIdx.x;
    const int lane = tid & 31, warp = tid >> 5;
    const int wm = warp >> 1, wn = warp & 1;

    const int z = blockIdx.z, zb = z / Hd, zh = z % Hd;
    const int row0 = blockIdx.y * BM, col0 = blockIdx.x * BN;
    const int lda2 = lda * 2, ldb2 = ldb * 2;
    const char* A = (const char*)(Ag + zb * oAb + zh * oAh) + (size_t)row0 * lda2;
    const char* B = (const char*)(Bg + zb * oBb + zh * oBh) + (size_t)col0 * ldb2;
    float* C = Cg + zb * oCb + zh * oCh;
    bf16* EA = expAg ? (expAg + (size_t)zb * oCb * 3 + (size_t)zh * oCh * 3) : (bf16*)0;
    const int lde = ldc * 3;

    float acc[2][NT][4];
#pragma unroll
    for (int i = 0; i < 2; i++)
#pragma unroll
        for (int j = 0; j < NT; j++)
#pragma unroll
            for (int k = 0; k < 4; k++) acc[i][j][k] = 0.f;

    auto load_stage = [&](int c) {
        int s = c & 1;
        uint32_t sa = sbase + s * ASTG;
        const char* Ac = A + c * 128;
#pragma unroll
        for (int i = 0; i < (BM * 8) / 256; i++) {
            int cc = tid + i * 256, r = cc >> 3, sg = (cc & 7) * 16;
            cpa16(sa + r * (LT * 2) + sg, Ac + (size_t)r * lda2 + sg);
        }
        uint32_t sb = sbase + 2 * ASTG + s * BSTG;
        const char* Bc = B + c * 128;
#pragma unroll
        for (int i = 0; i < (BN * 8) / 256; i++) {
            int cc = tid + i * 256, r = cc >> 3, sg = (cc & 7) * 16;
            cpa16(sb + r * (LT * 2) + sg, Bc + (size_t)r * ldb2 + sg);
        }
        asm volatile("cp.async.commit_group;\n");
    };

    load_stage(0);

    const int g = lane >> 3, ri = lane & 7;
    for (int c = 0; c < NC; c++) {
        if (c + 1 < NC) {
            load_stage(c + 1);
            asm volatile("cp.async.wait_group 1;\n");
        } else {
            asm volatile("cp.async.wait_group 0;\n");
        }
        __syncthreads();

        int s = c & 1;
        uint32_t sa = sbase + s * ASTG;
        uint32_t sb = sbase + 2 * ASTG + s * BSTG;
#pragma unroll
        for (int k16 = 0; k16 < 4; k16++) {
            uint32_t a[2][4];
#pragma unroll
            for (int mt = 0; mt < 2; mt++) {
                int row = wm * 32 + mt * 16 + ri + (g & 1) * 8;
                ldm_x4(a[mt][0], a[mt][1], a[mt][2], a[mt][3],
                       sa + row * (LT * 2) + k16 * 32 + (g >> 1) * 16);
            }
            uint32_t b[NT][2];
#pragma unroll
            for (int np = 0; np < NT / 2; np++) {
                int nrow = wn * (BN / 2) + np * 16 + ri + (g >> 1) * 8;
                ldm_x4(b[2 * np][0], b[2 * np][1], b[2 * np + 1][0], b[2 * np + 1][1],
                       sb + nrow * (LT * 2) + k16 * 32 + (g & 1) * 16);
            }
#pragma unroll
            for (int mt = 0; mt < 2; mt++)
#pragma unroll
                for (int nt = 0; nt < NT; nt++)
                    mma16816(acc[mt][nt], a[mt], b[nt]);
        }
        __syncthreads();
    }

    const int gq = lane >> 2, tq = lane & 3;
#pragma unroll
    for (int mt = 0; mt < 2; mt++) {
#pragma unroll
        for (int nt = 0; nt < NT; nt++) {
            int ccol = col0 + wn * (BN / 2) + nt * 8 + tq * 2;
#pragma unroll
            for (int h = 0; h < 2; h++) {
                int r = row0 + wm * 32 + mt * 16 + gq + h * 8;
                size_t off = (size_t)r * ldc + ccol;
                float v0 = alpha * acc[mt][nt][2 * h];
                float v1 = alpha * acc[mt][nt][2 * h + 1];
                if (beta != 0.f) {
                    float2 p = *(const float2*)&C[off];
                    v0 += beta * p.x; v1 += beta * p.y;
                }
                if (bias) { v0 += bias[ccol]; v1 += bias[ccol + 1]; }
                if (resid) {
                    float2 p = *(const float2*)&resid[off];
                    v0 += p.x; v1 += p.y;
                }
                float2 o; o.x = v0; o.y = v1;
                *(float2*)&C[off] = o;
                if (EA) {
                    bf16 h0 = __float2bfloat16(v0);
                    bf16 l0 = __float2bfloat16(v0 - __bfloat162float(h0));
                    bf16 h1 = __float2bfloat16(v1);
                    bf16 l1 = __float2bfloat16(v1 - __bfloat162float(h1));
                    uint32_t u0 = (uint32_t)bfbits(h0) | ((uint32_t)bfbits(l0) << 16);
                    uint32_t u1 = (uint32_t)bfbits(h0) | ((uint32_t)bfbits(h1) << 16);
                    uint32_t u2 = (uint32_t)bfbits(l1) | ((uint32_t)bfbits(h1) << 16);
                    uint32_t* q = (uint32_t*)(EA + (size_t)r * lde + 3 * ccol);
                    q[0] = u0; q[1] = u1; q[2] = u2;
                }
            }
        }
    }
}

// ---------------- setup + expansions ----------------
__global__ void setup_misc() {
    int t = threadIdx.x;
    double s = 0.0;
    for (int f = FLEFT; f < 256; ++f)
        s += 2.0 * cos(2.0 * PI_D * (double)f * (double)t / 512.0);
    s += (t & 1) ? -1.0 : 1.0;
    d_g[t] = (float)(s / 512.0);
}
__global__ void expand_G() {
    int l = blockIdx.x, m = threadIdx.x;
    float v = d_g[(l - m) & (NL - 1)];
    bf16 h = __float2bfloat16(v);
    bf16 lo = __float2bfloat16(v - __bfloat162float(h));
    bf16* d = d_Ge + (size_t)l * 1536 + 3 * m;
    d[0] = h; d[1] = lo; d[2] = h;
}
// PAT 0 = A-pattern (hi,lo,hi); PAT 1 = B-pattern (hi,hi,lo)
template <int PAT>
__global__ void expand_k(const float* __restrict__ src, bf16* __restrict__ dst,
                         int K, int src_ld, int Hd, long long oZb, long long oZh, long long dstZ) {
    int z = blockIdx.z, zb = z / Hd, zh = z % Hd;
    const float* s = src + zb * oZb + zh * oZh + (size_t)blockIdx.y * src_ld;
    bf16* d = dst + (size_t)z * dstZ + (size_t)blockIdx.y * (3 * K);
    for (int k = blockIdx.x * blockDim.x + threadIdx.x; k < K; k += gridDim.x * blockDim.x) {
        float v = s[k];
        bf16 h = __float2bfloat16(v);
        bf16 lo = __float2bfloat16(v - __bfloat162float(h));
        if (PAT == 0) { d[3*k] = h; d[3*k+1] = lo; d[3*k+2] = h; }
        else          { d[3*k] = h; d[3*k+1] = h;  d[3*k+2] = lo; }
    }
}
// transpose + B-pattern: src [Krows, Ncols] -> dst [Ncols, 3*Krows]
__global__ void texpand_b(const float* __restrict__ src, bf16* __restrict__ dst,
                          int src_ld, int Krows, int Ncols, int Hd,
                          long long oZb, long long oZh, long long dstZ) {
    __shared__ float t[32][33];
    int z = blockIdx.z, zb = z / Hd, zh = z % Hd;
    const float* s = src + zb * oZb + zh * oZh;
    bf16* d = dst + (size_t)z * dstZ;
    int k0 = blockIdx.x * 32, n0 = blockIdx.y * 32;
    int tx = threadIdx.x, ty = threadIdx.y;
#pragma unroll
    for (int i = 0; i < 32; i += 8)
        t[ty + i][tx] = s[(size_t)(k0 + ty + i) * src_ld + n0 + tx];
    __syncthreads();
#pragma unroll
    for (int i = 0; i < 32; i += 8) {
        int n = n0 + ty + i, k = k0 + tx;
        float v = t[tx][ty + i];
        bf16 h = __float2bfloat16(v);
        bf16 lo = __float2bfloat16(v - __bfloat162float(h));
        bf16* dd = d + (size_t)n * (3 * Krows) + 3 * k;
        dd[0] = h; dd[1] = h; dd[2] = lo;
    }
}

// ---------------- mean_value from scores: circular-diagonal sums ----------------
__global__ void diag_partial(const float* __restrict__ S) {
    int h = blockIdx.x, b = blockIdx.y;
    const float* Sz = S + ((size_t)(b * NH + h)) * NL * NL;
    __shared__ float bins[8][NL];
    int wid = threadIdx.x >> 5, lane = threadIdx.x & 31;
    for (int i = threadIdx.x; i < 8 * NL; i += 256) ((float*)bins)[i] = 0.f;
    __syncthreads();
    for (int r = wid; r < NL; r += 8) {
        const float* row = Sz + (size_t)r * NL;
        for (int j = lane; j < NL; j += 32)
            bins[wid][(r - j) & (NL - 1)] += row[j];
    }
    __syncthreads();
    for (int dd = threadIdx.x; dd < NL; dd += 256) {
        float a = 0.f;
#pragma unroll
        for (int w = 0; w < 8; w++) a += bins[w][dd];
        d_mvp[(b * NH + h) * NL + dd] = a;
    }
}
__global__ void topk_kernel() {
    int b = blockIdx.x, t = threadIdx.x;
    __shared__ float mv[NL], rv[256], selw[NTOPK];
    __shared__ int ri[256], seld[NTOPK];
    for (int d = t; d < NL; d += 256) {
        float s = 0.f;
#pragma unroll
        for (int h = 0; h < NH; h++) s += d_mvp[(b * NH + h) * NL + d];
        mv[d] = s * (1.f / 64.f);  // corr = 8*S, mean over 512 channels
    }
    __syncthreads();
    for (int k = 0; k < NTOPK; k++) {
        float best = -1e30f; int bi = NL;
        for (int d = t; d < NL; d += 256) {
            float x = mv[d];
            if (x > best || (x == best && d < bi)) { best = x; bi = d; }
        }
        rv[t] = best; ri[t] = bi;
        __syncthreads();
        for (int off = 128; off; off >>= 1) {
            if (t < off && (rv[t+off] > rv[t] || (rv[t+off] == rv[t] && ri[t+off] < ri[t]))) {
                rv[t] = rv[t+off]; ri[t] = ri[t+off];
            }
            __syncthreads();
        }
        if (t == 0) { selw[k] = rv[0]; seld[k] = ri[0]; mv[ri[0]] = -1e30f; }
        __syncthreads();
    }
    if (t == 0) {
        float m = selw[0], s = 0.f;
        for (int k = 0; k < NTOPK; k++) { float e = expf(selw[k] - m); selw[k] = e; s += e; }
        float inv = 1.f / s;
        for (int k = 0; k < NTOPK; k++) {
            d_w[b * NTOPK + k] = selw[k] * inv;
            d_delay[b * NTOPK + k] = seld[k];
        }
    }
}

__global__ void delay_agg(const float* __restrict__ V, float* __restrict__ ctx) {
    int l = blockIdx.x, b = blockIdx.y, t = threadIdx.x;
    __shared__ float w[NTOPK];
    __shared__ int dl[NTOPK];
    if (t < NTOPK) { w[t] = d_w[b * NTOPK + t]; dl[t] = d_delay[b * NTOPK + t]; }
    __syncthreads();
    const float* Vb = V + (size_t)b * NL * NHID + t;
    float acc = 0.f;
#pragma unroll 2
    for (int k = 0; k < NTOPK; k++)
        acc += w[k] * Vb[(size_t)((l + dl[k]) & (NL - 1)) * NHID];
    ctx[(size_t)b * NL * NHID + (size_t)l * NHID + t] = 0.5f * acc;
}

// softmax(+mask), emitting expanded A-pattern probs directly (S left untouched)
__global__ void softmax_se(const float* __restrict__ S, const float* __restrict__ mask,
                           bf16* __restrict__ Se) {
    size_t row = blockIdx.x;
    int b = (int)(row / (NH * NL)), i = (int)(row % NL);
    const float* s = S + row * NL;
    const float* mr = mask + (size_t)b * NL * NL + (size_t)i * NL;
    bf16* se = Se + row * 1536;
    int t = threadIdx.x;
    float v[4], mx = -1e30f;
#pragma unroll
    for (int k = 0; k < 4; k++) { v[k] = s[t + 128*k] + mr[t + 128*k]; mx = fmaxf(mx, v[k]); }
    __shared__ float red[32];
#pragma unroll
    for (int o = 16; o; o >>= 1) mx = fmaxf(mx, __shfl_xor_sync(~0u, mx, o));
    if ((t & 31) == 0) red[t >> 5] = mx;
    __syncthreads();
    mx = fmaxf(fmaxf(red[0], red[1]), fmaxf(red[2], red[3]));
    float sum = 0.f;
#pragma unroll
    for (int k = 0; k < 4; k++) { v[k] = expf(v[k] - mx); sum += v[k]; }
#pragma unroll
    for (int o = 16; o; o >>= 1) sum += __shfl_xor_sync(~0u, sum, o);
    __syncthreads();
    if ((t & 31) == 0) red[t >> 5] = sum;
    __syncthreads();
    float inv = 1.f / (red[0] + red[1] + red[2] + red[3]);
#pragma unroll
    for (int k = 0; k < 4; k++) {
        float p = v[k] * inv;
        int col = t + 128 * k;
        bf16 h = __float2bfloat16(p);
        bf16 lo = __float2bfloat16(p - __bfloat162float(h));
        se[3*col] = h; se[3*col + 1] = lo; se[3*col + 2] = h;
    }
}

__global__ void layernorm(const float* __restrict__ Hb, const float* __restrict__ w,
                          const float* __restrict__ bz, float* __restrict__ out) {
    size_t row = blockIdx.x;
    const float* h = Hb + row * NHID;
    float* o = out + row * NHID;
    int t = threadIdx.x;
    float v[4], s = 0.f;
#pragma unroll
    for (int k = 0; k < 4; k++) { v[k] = h[t + 128*k]; s += v[k]; }
    __shared__ float red[32];
#pragma unroll
    for (int o2 = 16; o2; o2 >>= 1) s += __shfl_xor_sync(~0u, s, o2);
    if ((t & 31) == 0) red[t >> 5] = s;
    __syncthreads();
    float mu = (red[0] + red[1] + red[2] + red[3]) / (float)NHID;
    float s2 = 0.f;
#pragma unroll
    for (int k = 0; k < 4; k++) { float d = v[k] - mu; s2 += d * d; }
#pragma unroll
    for (int o2 = 16; o2; o2 >>= 1) s2 += __shfl_xor_sync(~0u, s2, o2);
    __syncthreads();
    if ((t & 31) == 0) red[t >> 5] = s2;
    __syncthreads();
    float inv = rsqrtf((red[0] + red[1] + red[2] + red[3]) / (float)NHID + 1e-12f);
#pragma unroll
    for (int k = 0; k < 4; k++) {
        int c = t + 128*k;
        o[c] = w[c] * ((v[k] - mu) * inv) + bz[c];
    }
}

// ---------------- launch ----------------
extern "C" void kernel_launch(void* const* d_in, const int* in_sizes, int n_in,
                              void* d_out, int out_size) {
    (void)in_sizes; (void)n_in; (void)out_size;
    const float* x = (const float*)d_in[0];
    const float* mask = (const float*)d_in[1];
    const float* Wq = (const float*)d_in[2];
    const float* Wk = (const float*)d_in[4];
    const float* Wv = (const float*)d_in[6];
    const float* bv = (const float*)d_in[7];
    const float* Wd = (const float*)d_in[8];
    const float* bd = (const float*)d_in[9];
    const float* lnw = (const float*)d_in[10];
    const float* lnb = (const float*)d_in[11];
    float* out = (float*)d_out;

    bf16 *pWe, *pWde, *pxe, *pGe, *pxte, *pXge, *pQfe, *pKfe, *pVfte, *pSe, *pctxe;
    float *pXg, *pQKVf, *pV, *pS, *pctx, *pHb;
    cudaGetSymbolAddress((void**)&pWe, d_We);
    cudaGetSymbolAddress((void**)&pWde, d_Wde);
    cudaGetSymbolAddress((void**)&pxe, d_xe);
    cudaGetSymbolAddress((void**)&pGe, d_Ge);
    cudaGetSymbolAddress((void**)&pxte, d_xte);
    cudaGetSymbolAddress((void**)&pXge, d_Xge);
    cudaGetSymbolAddress((void**)&pQfe, d_Qfe);
    cudaGetSymbolAddress((void**)&pKfe, d_Kfe);
    cudaGetSymbolAddress((void**)&pVfte, d_Vfte);
    cudaGetSymbolAddress((void**)&pSe, d_Se);
    cudaGetSymbolAddress((void**)&pctxe, d_ctxe);
    cudaGetSymbolAddress((void**)&pXg, d_Xg);
    cudaGetSymbolAddress((void**)&pQKVf, d_QKVf);
    cudaGetSymbolAddress((void**)&pV, d_V);
    cudaGetSymbolAddress((void**)&pS, d_S);
    cudaGetSymbolAddress((void**)&pctx, d_ctx);
    cudaGetSymbolAddress((void**)&pHb, d_Hb);

    const int SM128 = (2 * 128 + 2 * 128) * 72 * 2;  // 73728 B
    const int SM64  = (2 * 128 + 2 * 64) * 72 * 2;   // 55296 B
    cudaFuncSetAttribute(bgemm<128>, cudaFuncAttributeMaxDynamicSharedMemorySize, SM128);
    cudaFuncSetAttribute(bgemm<64>,  cudaFuncAttributeMaxDynamicSharedMemorySize, SM64);

    const long long L1536 = 1536LL * 512;   // per-batch stride of [512,1536] buffers
    const long long BLH = 512LL * 512;
    const long long BLL = 512LL * 512;

    setup_misc<<<1, 512>>>();
    expand_G<<<512, 512>>>();
    expand_k<1><<<dim3(2,512,1), 256>>>(Wq, pWe,             512, 512, 1, 0, 0, 0);
    expand_k<1><<<dim3(2,512,1), 256>>>(Wk, pWe + 512*1536,  512, 512, 1, 0, 0, 0);
    expand_k<1><<<dim3(2,512,1), 256>>>(Wv, pWe + 1024*1536, 512, 512, 1, 0, 0, 0);
    expand_k<1><<<dim3(2,512,1), 256>>>(Wd, pWde,            512, 512, 1, 0, 0, 0);
    expand_k<0><<<dim3(2,16384,1), 256>>>(x, pxe,            512, 512, 1, 0, 0, 0);
    // x^T expanded per batch (B operand of the filter GEMM)
    texpand_b<<<dim3(16,16,32), dim3(32,8)>>>(x, pxte, 512, 512, 512, 1,
        BLH, 0, 512LL*1536);

    // 1) filter X: Xg[b] = G @ x[b]   (emits Xge expanded via epilogue)
    bgemm<128><<<dim3(4,4,32), 256, SM128>>>(pGe, pxte, pXg,
        1536, 1536, 512, 1536, 0,0, 512LL*1536,0, BLH,0, 1,
        nullptr, nullptr, pXge, 1.f, 0.f);

    // 2) filtered projections: QKVf = Xg @ [Wq;Wk;Wv]^T   (band kills bias exactly)
    bgemm<128><<<dim3(12,128,1), 256, SM128>>>(pXge, pWe, pQKVf,
        1536, 1536, 1536, 1536, 0,0, 0,0, 0,0, 1, nullptr, nullptr, nullptr, 1.f, 0.f);

    // 3) unfiltered V (time branch): V = x @ Wv^T + bv
    bgemm<128><<<dim3(4,128,1), 256, SM128>>>(pxe, pWe + 1024*1536, pV,
        1536, 1536, 512, 1536, 0,0, 0,0, 0,0, 1, bv, nullptr, nullptr, 1.f, 0.f);

    // per-head expansions from QKVf (Qf cols 0-511, Kf 512-1023, Vf 1024-1535)
    expand_k<0><<<dim3(1,512,256), 64>>>(pQKVf, pQfe, 64, 1536, 8, L1536, 64, 512LL*192);
    expand_k<1><<<dim3(1,512,256), 64>>>(pQKVf + 512, pKfe, 64, 1536, 8, L1536, 64, 512LL*192);
    texpand_b<<<dim3(16,2,256), dim3(32,8)>>>(pQKVf + 1024, pVfte, 1536, 512, 64, 8,
        L1536, 64, 64LL*1536);

    // 4) scores: S[z] = 0.125 * Qf_h @ Kf_h^T
    bgemm<128><<<dim3(4,4,256), 256, SM128>>>(pQfe, pKfe, pS,
        192, 192, 512, 192, 8*512LL*192, 512LL*192, 8*512LL*192, 512LL*192,
        8*BLL, BLL, 8, nullptr, nullptr, nullptr, 0.125f, 0.f);

    // mean_value from S diagonals; top-k; weights
    diag_partial<<<dim3(NH, NB), 256>>>(pS);
    topk_kernel<<<NB, 256>>>();

    // time branch gather
    delay_agg<<<dim3(NL, NB), NHID>>>(pV, pctx);

    // softmax (+mask) -> expanded probs Se
    softmax_se<<<NB * NH * NL, 128>>>(pS, mask, pSe);

    // 5) ctx += 0.5 * probs @ Vf_h   (emits ctxe expanded via epilogue)
    bgemm<64><<<dim3(1,4,256), 256, SM64>>>(pSe, pVfte, pctx,
        1536, 1536, 512, 1536, 8*512LL*1536, 512LL*1536, 8*64LL*1536, 64LL*1536,
        BLH, 64, 8, nullptr, nullptr, pctxe, 0.5f, 1.f);

    // 6) output projection + bias + residual
    bgemm<128><<<dim3(4,128,1), 256, SM128>>>(pctxe, pWde, pHb,
        1536, 1536, 512, 1536, 0,0, 0,0, 0,0, 1, bd, x, nullptr, 1.f, 0.f);

    layernorm<<<NB * NL, 128>>>(pHb, lnw, lnb, out);
}

// round 9
// speedup vs baseline: 2.0335x; 1.0259x over previous
#include <cuda_runtime.h>
#include <cuda_bf16.h>
#include <math.h>
#include <stdint.h>

#define NB 32
#define NL 512
#define NHID 512
#define NH 8
#define NE 64
#define NTOPK 62
#define FLEFT 102
#define PI_D 3.14159265358979323846

typedef __nv_bfloat16 bf16;

// ---------------- static device scratch ----------------
__device__ float d_g[NL];
__device__ bf16 d_We[1536 * 1536];                 // [Wq;Wk;Wv] expanded (B-pattern, 3-term)
__device__ bf16 d_Wde[512 * 1536];                 // Wd expanded (B-pattern)
__device__ bf16 d_xe[16384 * 1536];                // x expanded (A-pattern)
__device__ bf16 d_Ge[512 * 1536];                  // G expanded (A-pattern)
__device__ bf16 d_xte[(size_t)NB * 512 * 1536];    // x^T expanded (B-pattern), per batch
__device__ bf16 d_Xge[16384 * 1536];               // filtered X expanded (A-pattern, via expA)
__device__ float d_QKVf[(size_t)16384 * 1536];     // Qf|Kf|Vf (f32)
__device__ float d_V[(size_t)16384 * 512];         // unfiltered V (time branch)
__device__ bf16 d_Qfe[(size_t)NB * NH * NL * 192];
__device__ bf16 d_Kfe[(size_t)NB * NH * NL * 192];
__device__ bf16 d_Vfte[(size_t)NB * NH * NE * 1024]; // V^T 2-term (hi,hi)
__device__ bf16 d_S[(size_t)NB * NH * NL * NL];    // raw scores, bf16
__device__ bf16 d_Se[(size_t)NB * NH * NL * 1024]; // probs 2-term (hi,lo)
__device__ float d_ctx[(size_t)16384 * 512];
__device__ bf16 d_ctxe[(size_t)16384 * 1536];      // ctx expanded (A-pattern, via expA)
__device__ float d_Hb[(size_t)16384 * 512];
__device__ float d_mvp[(size_t)NB * NH * 16 * NL]; // per-CTA diag partials
__device__ int d_delay[NB * NTOPK];
__device__ float d_w[NB * NTOPK];

// ---------------- helpers ----------------
__device__ __forceinline__ uint32_t smem_u32(const void* p) {
    uint32_t r;
    asm("{ .reg .u64 t; cvta.to.shared.u64 t, %1; cvt.u32.u64 %0, t; }" : "=r"(r) : "l"(p));
    return r;
}
__device__ __forceinline__ void cpa16(uint32_t s, const void* g) {
    asm volatile("cp.async.cg.shared.global [%0], [%1], 16;\n" :: "r"(s), "l"(g));
}
__device__ __forceinline__ void ldm_x4(uint32_t& r0, uint32_t& r1, uint32_t& r2, uint32_t& r3,
                                       uint32_t a) {
    asm volatile("ldmatrix.sync.aligned.m8n8.x4.shared.b16 {%0,%1,%2,%3}, [%4];\n"
                 : "=r"(r0), "=r"(r1), "=r"(r2), "=r"(r3) : "r"(a));
}
__device__ __forceinline__ void mma16816(float* c, const uint32_t* a, const uint32_t* b) {
    asm volatile(
        "mma.sync.aligned.m16n8k16.row.col.f32.bf16.bf16.f32 "
        "{%0,%1,%2,%3},{%4,%5,%6,%7},{%8,%9},{%0,%1,%2,%3};\n"
        : "+f"(c[0]), "+f"(c[1]), "+f"(c[2]), "+f"(c[3])
        : "r"(a[0]), "r"(a[1]), "r"(a[2]), "r"(a[3]), "r"(b[0]), "r"(b[1]));
}
__device__ __forceinline__ unsigned short bfbits(bf16 h) {
    return __bfloat16_as_ushort(h);
}

// ---------------- bf16 HMMA NT GEMM over expanded-K operands ----------------
// C = alpha*A·B^T (+beta*C)(+bias)(+resid); optional expA (3-term A-pattern output),
// optional bf16 C (c_bf16), optional per-CTA diagonal partial sums (diag).
template <int BN>
__global__ void __launch_bounds__(256, 2) bgemm(
    const bf16* __restrict__ Ag, const bf16* __restrict__ Bg, float* __restrict__ Cg,
    int lda, int ldb, int ldc, int Kx,
    long long oAb, long long oAh, long long oBb, long long oBh,
    long long oCb, long long oCh, int Hd,
    const float* __restrict__ bias, const float* __restrict__ resid,
    bf16* __restrict__ expAg, float* __restrict__ diag, int c_bf16,
    float alpha, float beta)
{
    constexpr int BM = 128, LT = 72;
    constexpr int ASTG = BM * LT * 2;
    constexpr int BSTG = BN * LT * 2;
    constexpr int NT = BN / 16;
    const int NC = Kx >> 6;

    extern __shared__ bf16 sm[];
    const uint32_t sbase = smem_u32(sm);

    const int tid = threadIdx.x;
    const int lane = tid & 31, warp = tid >> 5;
    const int wm = warp >> 1, wn = warp & 1;

    const int z = blockIdx.z, zb = z / Hd, zh = z % Hd;
    const int row0 = blockIdx.y * BM, col0 = blockIdx.x * BN;
    const int lda2 = lda * 2, ldb2 = ldb * 2;
    const char* A = (const char*)(Ag + zb * oAb + zh * oAh) + (size_t)row0 * lda2;
    const char* B = (const char*)(Bg + zb * oBb + zh * oBh) + (size_t)col0 * ldb2;
    float* C = (!c_bf16 && Cg) ? (Cg + zb * oCb + zh * oCh) : (float*)0;
    bf16* Cb = (c_bf16 && Cg) ? ((bf16*)Cg + zb * oCb + zh * oCh) : (bf16*)0;
    bf16* EA = expAg ? (expAg + (size_t)zb * oCb * 3 + (size_t)zh * oCh * 3) : (bf16*)0;
    const int lde = ldc * 3;

    float acc[2][NT][4];
#pragma unroll
    for (int i = 0; i < 2; i++)
#pragma unroll
        for (int j = 0; j < NT; j++)
#pragma unroll
            for (int k = 0; k < 4; k++) acc[i][j][k] = 0.f;

    auto load_stage = [&](int c) {
        int s = c & 1;
        uint32_t sa = sbase + s * ASTG;
        const char* Ac = A + c * 128;
#pragma unroll
        for (int i = 0; i < (BM * 8) / 256; i++) {
            int cc = tid + i * 256, r = cc >> 3, sg = (cc & 7) * 16;
            cpa16(sa + r * (LT * 2) + sg, Ac + (size_t)r * lda2 + sg);
        }
        uint32_t sb = sbase + 2 * ASTG + s * BSTG;
        const char* Bc = B + c * 128;
#pragma unroll
        for (int i = 0; i < (BN * 8) / 256; i++) {
            int cc = tid + i * 256, r = cc >> 3, sg = (cc & 7) * 16;
            cpa16(sb + r * (LT * 2) + sg, Bc + (size_t)r * ldb2 + sg);
        }
        asm volatile("cp.async.commit_group;\n");
    };

    load_stage(0);

    const int g = lane >> 3, ri = lane & 7;
    for (int c = 0; c < NC; c++) {
        if (c + 1 < NC) {
            load_stage(c + 1);
            asm volatile("cp.async.wait_group 1;\n");
        } else {
            asm volatile("cp.async.wait_group 0;\n");
        }
        __syncthreads();

        int s = c & 1;
        uint32_t sa = sbase + s * ASTG;
        uint32_t sb = sbase + 2 * ASTG + s * BSTG;
#pragma unroll
        for (int k16 = 0; k16 < 4; k16++) {
            uint32_t a[2][4];
#pragma unroll
            for (int mt = 0; mt < 2; mt++) {
                int row = wm * 32 + mt * 16 + ri + (g & 1) * 8;
                ldm_x4(a[mt][0], a[mt][1], a[mt][2], a[mt][3],
                       sa + row * (LT * 2) + k16 * 32 + (g >> 1) * 16);
            }
            uint32_t b[NT][2];
#pragma unroll
            for (int np = 0; np < NT / 2; np++) {
                int nrow = wn * (BN / 2) + np * 16 + ri + (g >> 1) * 8;
                ldm_x4(b[2 * np][0], b[2 * np][1], b[2 * np + 1][0], b[2 * np + 1][1],
                       sb + nrow * (LT * 2) + k16 * 32 + (g & 1) * 16);
            }
#pragma unroll
            for (int mt = 0; mt < 2; mt++)
#pragma unroll
                for (int nt = 0; nt < NT; nt++)
                    mma16816(acc[mt][nt], a[mt], b[nt]);
        }
        __syncthreads();
    }

    // epilogue
    float* bins = (float*)sm;  // mainloop smem is dead now
    if (diag) {
        for (int i = tid; i < 512; i += 256) bins[i] = 0.f;
        __syncthreads();
    }
    const int gq = lane >> 2, tq = lane & 3;
#pragma unroll
    for (int mt = 0; mt < 2; mt++) {
#pragma unroll
        for (int nt = 0; nt < NT; nt++) {
            int ccol = col0 + wn * (BN / 2) + nt * 8 + tq * 2;
#pragma unroll
            for (int h = 0; h < 2; h++) {
                int r = row0 + wm * 32 + mt * 16 + gq + h * 8;
                size_t off = (size_t)r * ldc + ccol;
                float v0 = alpha * acc[mt][nt][2 * h];
                float v1 = alpha * acc[mt][nt][2 * h + 1];
                if (beta != 0.f && C) {
                    float2 p = *(const float2*)&C[off];
                    v0 += beta * p.x; v1 += beta * p.y;
                }
                if (bias) { v0 += bias[ccol]; v1 += bias[ccol + 1]; }
                if (resid) {
                    float2 p = *(const float2*)&resid[off];
                    v0 += p.x; v1 += p.y;
                }
                if (C) {
                    float2 o; o.x = v0; o.y = v1;
                    *(float2*)&C[off] = o;
                }
                if (Cb) {
                    uint32_t pk = (uint32_t)bfbits(__float2bfloat16(v0)) |
                                  ((uint32_t)bfbits(__float2bfloat16(v1)) << 16);
                    *(uint32_t*)&Cb[off] = pk;
                }
                if (diag) {
                    atomicAdd(&bins[(r - ccol) & 511], v0);
                    atomicAdd(&bins[(r - ccol - 1) & 511], v1);
                }
                if (EA) {
                    bf16 h0 = __float2bfloat16(v0);
                    bf16 l0 = __float2bfloat16(v0 - __bfloat162float(h0));
                    bf16 h1 = __float2bfloat16(v1);
                    bf16 l1 = __float2bfloat16(v1 - __bfloat162float(h1));
                    uint32_t u0 = (uint32_t)bfbits(h0) | ((uint32_t)bfbits(l0) << 16);
                    uint32_t u1 = (uint32_t)bfbits(h0) | ((uint32_t)bfbits(h1) << 16);
                    uint32_t u2 = (uint32_t)bfbits(l1) | ((uint32_t)bfbits(h1) << 16);
                    uint32_t* q = (uint32_t*)(EA + (size_t)r * lde + 3 * ccol);
                    q[0] = u0; q[1] = u1; q[2] = u2;
                }
            }
        }
    }
    if (diag) {
        __syncthreads();
        int slot = z * (gridDim.x * gridDim.y) + blockIdx.y * gridDim.x + blockIdx.x;
        float* dd = diag + (size_t)slot * 512;
        for (int i = tid; i < 512; i += 256) dd[i] = bins[i];
    }
}

// ---------------- setup + expansions ----------------
__global__ void setup_misc() {
    int t = threadIdx.x;
    double s = 0.0;
    for (int f = FLEFT; f < 256; ++f)
        s += 2.0 * cos(2.0 * PI_D * (double)f * (double)t / 512.0);
    s += (t & 1) ? -1.0 : 1.0;
    d_g[t] = (float)(s / 512.0);
}
__global__ void expand_G() {
    int l = blockIdx.x, m = threadIdx.x;
    float v = d_g[(l - m) & (NL - 1)];
    bf16 h = __float2bfloat16(v);
    bf16 lo = __float2bfloat16(v - __bfloat162float(h));
    bf16* d = d_Ge + (size_t)l * 1536 + 3 * m;
    d[0] = h; d[1] = lo; d[2] = h;
}
// PAT 0 = A-pattern (hi,lo,hi); PAT 1 = B-pattern (hi,hi,lo)
template <int PAT>
__global__ void expand_k(const float* __restrict__ src, bf16* __restrict__ dst,
                         int K, int src_ld, int Hd, long long oZb, long long oZh, long long dstZ) {
    int z = blockIdx.z, zb = z / Hd, zh = z % Hd;
    const float* s = src + zb * oZb + zh * oZh + (size_t)blockIdx.y * src_ld;
    bf16* d = dst + (size_t)z * dstZ + (size_t)blockIdx.y * (3 * K);
    for (int k = blockIdx.x * blockDim.x + threadIdx.x; k < K; k += gridDim.x * blockDim.x) {
        float v = s[k];
        bf16 h = __float2bfloat16(v);
        bf16 lo = __float2bfloat16(v - __bfloat162float(h));
        if (PAT == 0) { d[3*k] = h; d[3*k+1] = lo; d[3*k+2] = h; }
        else          { d[3*k] = h; d[3*k+1] = h;  d[3*k+2] = lo; }
    }
}
// transpose + B-pattern (TERMS=3: hi,hi,lo; TERMS=2: hi,hi): src [Krows,Ncols] -> dst [Ncols,TERMS*Krows]
template <int TERMS>
__global__ void texpand_b(const float* __restrict__ src, bf16* __restrict__ dst,
                          int src_ld, int Krows, int Ncols, int Hd,
                          long long oZb, long long oZh, long long dstZ) {
    __shared__ float t[32][33];
    int z = blockIdx.z, zb = z / Hd, zh = z % Hd;
    const float* s = src + zb * oZb + zh * oZh;
    bf16* d = dst + (size_t)z * dstZ;
    int k0 = blockIdx.x * 32, n0 = blockIdx.y * 32;
    int tx = threadIdx.x, ty = threadIdx.y;
#pragma unroll
    for (int i = 0; i < 32; i += 8)
        t[ty + i][tx] = s[(size_t)(k0 + ty + i) * src_ld + n0 + tx];
    __syncthreads();
#pragma unroll
    for (int i = 0; i < 32; i += 8) {
        int n = n0 + ty + i, k = k0 + tx;
        float v = t[tx][ty + i];
        bf16 h = __float2bfloat16(v);
        bf16* dd = d + (size_t)n * (TERMS * Krows) + TERMS * k;
        dd[0] = h; dd[1] = h;
        if (TERMS == 3) dd[2] = __float2bfloat16(v - __bfloat162float(h));
    }
}

// ---------------- top-k over per-CTA diag partials ----------------
__global__ void topk_kernel() {
    int b = blockIdx.x, t = threadIdx.x;
    __shared__ float mv[NL], rv[256], selw[NTOPK];
    __shared__ int ri[256], seld[NTOPK];
    for (int d = t; d < NL; d += 256) {
        float s = 0.f;
        for (int sl = 0; sl < 128; sl++) s += d_mvp[((size_t)b * 128 + sl) * 512 + d];
        mv[d] = s * (1.f / 64.f);  // corr = 8*S, mean over 512 channels
    }
    __syncthreads();
    for (int k = 0; k < NTOPK; k++) {
        float best = -1e30f; int bi = NL;
        for (int d = t; d < NL; d += 256) {
            float x = mv[d];
            if (x > best || (x == best && d < bi)) { best = x; bi = d; }
        }
        rv[t] = best; ri[t] = bi;
        __syncthreads();
        for (int off = 128; off; off >>= 1) {
            if (t < off && (rv[t+off] > rv[t] || (rv[t+off] == rv[t] && ri[t+off] < ri[t]))) {
                rv[t] = rv[t+off]; ri[t] = ri[t+off];
            }
            __syncthreads();
        }
        if (t == 0) { selw[k] = rv[0]; seld[k] = ri[0]; mv[ri[0]] = -1e30f; }
        __syncthreads();
    }
    if (t == 0) {
        float m = selw[0], s = 0.f;
        for (int k = 0; k < NTOPK; k++) { float e = expf(selw[k] - m); selw[k] = e; s += e; }
        float inv = 1.f / s;
        for (int k = 0; k < NTOPK; k++) {
            d_w[b * NTOPK + k] = selw[k] * inv;
            d_delay[b * NTOPK + k] = seld[k];
        }
    }
}

__global__ void delay_agg(const float* __restrict__ V, float* __restrict__ ctx) {
    int l = blockIdx.x, b = blockIdx.y, t = threadIdx.x;
    __shared__ float w[NTOPK];
    __shared__ int dl[NTOPK];
    if (t < NTOPK) { w[t] = d_w[b * NTOPK + t]; dl[t] = d_delay[b * NTOPK + t]; }
    __syncthreads();
    const float* Vb = V + (size_t)b * NL * NHID + t;
    float acc = 0.f;
#pragma unroll 2
    for (int k = 0; k < NTOPK; k++)
        acc += w[k] * Vb[(size_t)((l + dl[k]) & (NL - 1)) * NHID];
    ctx[(size_t)b * NL * NHID + (size_t)l * NHID + t] = 0.5f * acc;
}

// softmax(+mask) over bf16 scores, emitting 2-term (hi,lo) expanded probs
__global__ void softmax_se(const bf16* __restrict__ S, const float* __restrict__ mask,
                           bf16* __restrict__ Se) {
    size_t row = blockIdx.x;
    int b = (int)(row / (NH * NL)), i = (int)(row % NL);
    const bf16* s = S + row * NL;
    const float* mr = mask + (size_t)b * NL * NL + (size_t)i * NL;
    bf16* se = Se + row * 1024;
    int t = threadIdx.x;
    float v[4], mx = -1e30f;
#pragma unroll
    for (int k = 0; k < 4; k++) {
        v[k] = __bfloat162float(s[t + 128*k]) + mr[t + 128*k];
        mx = fmaxf(mx, v[k]);
    }
    __shared__ float red[32];
#pragma unroll
    for (int o = 16; o; o >>= 1) mx = fmaxf(mx, __shfl_xor_sync(~0u, mx, o));
    if ((t & 31) == 0) red[t >> 5] = mx;
    __syncthreads();
    mx = fmaxf(fmaxf(red[0], red[1]), fmaxf(red[2], red[3]));
    float sum = 0.f;
#pragma unroll
    for (int k = 0; k < 4; k++) { v[k] = expf(v[k] - mx); sum += v[k]; }
#pragma unroll
    for (int o = 16; o; o >>= 1) sum += __shfl_xor_sync(~0u, sum, o);
    __syncthreads();
    if ((t & 31) == 0) red[t >> 5] = sum;
    __syncthreads();
    float inv = 1.f / (red[0] + red[1] + red[2] + red[3]);
#pragma unroll
    for (int k = 0; k < 4; k++) {
        float p = v[k] * inv;
        int col = t + 128 * k;
        bf16 h = __float2bfloat16(p);
        bf16 lo = __float2bfloat16(p - __bfloat162float(h));
        uint32_t pk = (uint32_t)bfbits(h) | ((uint32_t)bfbits(lo) << 16);
        *(uint32_t*)&se[2 * col] = pk;
    }
}

__global__ void layernorm(const float* __restrict__ Hb, const float* __restrict__ w,
                          const float* __restrict__ bz, float* __restrict__ out) {
    size_t row = blockIdx.x;
    const float* h = Hb + row * NHID;
    float* o = out + row * NHID;
    int t = threadIdx.x;
    float v[4], s = 0.f;
#pragma unroll
    for (int k = 0; k < 4; k++) { v[k] = h[t + 128*k]; s += v[k]; }
    __shared__ float red[32];
#pragma unroll
    for (int o2 = 16; o2; o2 >>= 1) s += __shfl_xor_sync(~0u, s, o2);
    if ((t & 31) == 0) red[t >> 5] = s;
    __syncthreads();
    float mu = (red[0] + red[1] + red[2] + red[3]) / (float)NHID;
    float s2 = 0.f;
#pragma unroll
    for (int k = 0; k < 4; k++) { float d = v[k] - mu; s2 += d * d; }
#pragma unroll
    for (int o2 = 16; o2; o2 >>= 1) s2 += __shfl_xor_sync(~0u, s2, o2);
    __syncthreads();
    if ((t & 31) == 0) red[t >> 5] = s2;
    __syncthreads();
    float inv = rsqrtf((red[0] + red[1] + red[2] + red[3]) / (float)NHID + 1e-12f);
#pragma unroll
    for (int k = 0; k < 4; k++) {
        int c = t + 128*k;
        o[c] = w[c] * ((v[k] - mu) * inv) + bz[c];
    }
}

// ---------------- launch ----------------
extern "C" void kernel_launch(void* const* d_in, const int* in_sizes, int n_in,
                              void* d_out, int out_size) {
    (void)in_sizes; (void)n_in; (void)out_size;
    const float* x = (const float*)d_in[0];
    const float* mask = (const float*)d_in[1];
    const float* Wq = (const float*)d_in[2];
    const float* Wk = (const float*)d_in[4];
    const float* Wv = (const float*)d_in[6];
    const float* bv = (const float*)d_in[7];
    const float* Wd = (const float*)d_in[8];
    const float* bd = (const float*)d_in[9];
    const float* lnw = (const float*)d_in[10];
    const float* lnb = (const float*)d_in[11];
    float* out = (float*)d_out;

    bf16 *pWe, *pWde, *pxe, *pGe, *pxte, *pXge, *pQfe, *pKfe, *pVfte, *pSb, *pSe, *pctxe;
    float *pQKVf, *pV, *pctx, *pHb, *pmvp;
    cudaGetSymbolAddress((void**)&pWe, d_We);
    cudaGetSymbolAddress((void**)&pWde, d_Wde);
    cudaGetSymbolAddress((void**)&pxe, d_xe);
    cudaGetSymbolAddress((void**)&pGe, d_Ge);
    cudaGetSymbolAddress((void**)&pxte, d_xte);
    cudaGetSymbolAddress((void**)&pXge, d_Xge);
    cudaGetSymbolAddress((void**)&pQfe, d_Qfe);
    cudaGetSymbolAddress((void**)&pKfe, d_Kfe);
    cudaGetSymbolAddress((void**)&pVfte, d_Vfte);
    cudaGetSymbolAddress((void**)&pSb, d_S);
    cudaGetSymbolAddress((void**)&pSe, d_Se);
    cudaGetSymbolAddress((void**)&pctxe, d_ctxe);
    cudaGetSymbolAddress((void**)&pQKVf, d_QKVf);
    cudaGetSymbolAddress((void**)&pV, d_V);
    cudaGetSymbolAddress((void**)&pctx, d_ctx);
    cudaGetSymbolAddress((void**)&pHb, d_Hb);
    cudaGetSymbolAddress((void**)&pmvp, d_mvp);

    const int SM128 = (2 * 128 + 2 * 128) * 72 * 2;  // 73728 B
    const int SM64  = (2 * 128 + 2 * 64) * 72 * 2;   // 55296 B
    cudaFuncSetAttribute(bgemm<128>, cudaFuncAttributeMaxDynamicSharedMemorySize, SM128);
    cudaFuncSetAttribute(bgemm<64>,  cudaFuncAttributeMaxDynamicSharedMemorySize, SM64);

    const long long L1536 = 1536LL * 512;
    const long long BLH = 512LL * 512;
    const long long BLL = 512LL * 512;

    setup_misc<<<1, 512>>>();
    expand_G<<<512, 512>>>();
    expand_k<1><<<dim3(2,512,1), 256>>>(Wq, pWe,             512, 512, 1, 0, 0, 0);
    expand_k<1><<<dim3(2,512,1), 256>>>(Wk, pWe + 512*1536,  512, 512, 1, 0, 0, 0);
    expand_k<1><<<dim3(2,512,1), 256>>>(Wv, pWe + 1024*1536, 512, 512, 1, 0, 0, 0);
    expand_k<1><<<dim3(2,512,1), 256>>>(Wd, pWde,            512, 512, 1, 0, 0, 0);
    expand_k<0><<<dim3(2,16384,1), 256>>>(x, pxe,            512, 512, 1, 0, 0, 0);
    // x^T expanded per batch (B operand of the filter GEMM)
    texpand_b<3><<<dim3(16,16,32), dim3(32,8)>>>(x, pxte, 512, 512, 512, 1,
        BLH, 0, 512LL*1536);

    // 1) filter X: Xge = expand(G @ x[b])  (C store skipped; only expA emitted)
    bgemm<128><<<dim3(4,4,32), 256, SM128>>>(pGe, pxte, nullptr,
        1536, 1536, 512, 1536, 0,0, 512LL*1536,0, BLH,0, 1,
        nullptr, nullptr, pXge, nullptr, 0, 1.f, 0.f);

    // 2) filtered projections: QKVf = Xg @ [Wq;Wk;Wv]^T  (band kills bias exactly)
    bgemm<128><<<dim3(12,128,1), 256, SM128>>>(pXge, pWe, pQKVf,
        1536, 1536, 1536, 1536, 0,0, 0,0, 0,0, 1,
        nullptr, nullptr, nullptr, nullptr, 0, 1.f, 0.f);

    // 3) unfiltered V (time branch): V = x @ Wv^T + bv
    bgemm<128><<<dim3(4,128,1), 256, SM128>>>(pxe, pWe + 1024*1536, pV,
        1536, 1536, 512, 1536, 0,0, 0,0, 0,0, 1,
        bv, nullptr, nullptr, nullptr, 0, 1.f, 0.f);

    // per-head expansions from QKVf
    expand_k<0><<<dim3(1,512,256), 64>>>(pQKVf, pQfe, 64, 1536, 8, L1536, 64, 512LL*192);
    expand_k<1><<<dim3(1,512,256), 64>>>(pQKVf + 512, pKfe, 64, 1536, 8, L1536, 64, 512LL*192);
    texpand_b<2><<<dim3(16,2,256), dim3(32,8)>>>(pQKVf + 1024, pVfte, 1536, 512, 64, 8,
        L1536, 64, 64LL*1024);

    // 4) scores: S(bf16) = 0.125 * Qf_h @ Kf_h^T, with fused per-CTA diag partials
    bgemm<128><<<dim3(4,4,256), 256, SM128>>>(pQfe, pKfe, (float*)pSb,
        192, 192, 512, 192, 8*512LL*192, 512LL*192, 8*512LL*192, 512LL*192,
        8*BLL, BLL, 8, nullptr, nullptr, nullptr, pmvp, 1, 0.125f, 0.f);

    // top-k over summed diag partials
    topk_kernel<<<NB, 256>>>();

    // time branch gather
    delay_agg<<<dim3(NL, NB), NHID>>>(pV, pctx);

    // softmax (+mask) -> 2-term expanded probs Se
    softmax_se<<<NB * NH * NL, 128>>>(pSb, mask, pSe);

    // 5) ctx += 0.5 * probs @ Vf_h  (2-term, Kx=1024; emits ctxe via epilogue)
    bgemm<64><<<dim3(1,4,256), 256, SM64>>>(pSe, pVfte, pctx,
        1024, 1024, 512, 1024, 8*512LL*1024, 512LL*1024, 8*64LL*1024, 64LL*1024,
        BLH, 64, 8, nullptr, nullptr, pctxe, nullptr, 0, 0.5f, 1.f);

    // 6) output projection + bias + residual
    bgemm<128><<<dim3(4,128,1), 256, SM128>>>(pctxe, pWde, pHb,
        1536, 1536, 512, 1536, 0,0, 0,0, 0,0, 1,
        bd, x, nullptr, nullptr, 0, 1.f, 0.f);

    layernorm<<<NB * NL, 128>>>(pHb, lnw, lnb, out);
}